// round 15
// baseline (speedup 1.0000x reference)
#include <cuda_runtime.h>

// ---------------------------------------------------------------------------
// Decoder step: attention (B=128, L=2048, H=256) + 2x LSTM cell.
//
// attn_kernel : flash softmax, grid = 128 x 2 L-splits = 256 blocks (single
//               wave). NEW: encoder rows stream through a depth-5 cp.async
//               smem ring (16KB stages = 16 rows), decoupling load issue from
//               the dot/shfl/exp chain (~48KB in flight per block vs 16KB of
//               register prefetch). One syncthreads + wait_group<3> per
//               stage, 64 stages. Fixed-offset exp (accuracy-proven).
//               Fused last-arriver combine + transposed packing (R10 protocol).
// lstm_full<L>: R13 verbatim. grid=128, 2 h-indices (8 gate rows) x 128
//               batches, warps split K 8-ways, X pipelined LDG.128,
//               W via cp.async, Ws/Rs overlaid.
// ---------------------------------------------------------------------------

#define B_ 128
#define H_ 256
#define L_ 2048
#define NSPLIT 2
#define LSP (L_ / NSPLIT)           // 1024 rows per split
#define ATTN_BLOCKS (B_ * NSPLIT)   // 256 — single wave
#define M0 44.0f
#define NSTAGE 5                    // ring depth (buffers)
#define ROWS_PER_STAGE 16
#define STAGE_FLOATS (ROWS_PER_STAGE * H_)      // 4096
#define NSTAGES_TOTAL (LSP / ROWS_PER_STAGE)    // 64
#define ATTN_SMEM (NSTAGE * STAGE_FLOATS * 4)   // 81920 bytes dynamic

__device__ float g_X1T[512 * 128];   // rows 0-255 ctx, 256-511 hidden1
__device__ float g_X2T[768 * 128];   // rows 0-255 embed, 256-511 h1, 512-767 hidden2
__device__ float g_ctx_part[ATTN_BLOCKS * H_];
__device__ float g_d[ATTN_BLOCKS];
__device__ unsigned g_cnt[B_];       // zero-init; self-resetting

// ---------------- helpers ----------------------------------------------------

__device__ __forceinline__ float sigmoidf_(float x) {
    return 1.f / (1.f + __expf(-x));
}

__device__ __forceinline__ void cp_async16(void* smem_dst, const void* gmem_src) {
    unsigned saddr = (unsigned)__cvta_generic_to_shared(smem_dst);
    asm volatile("cp.async.cg.shared.global [%0], [%1], 16;\n"
                 :: "r"(saddr), "l"(gmem_src));
}
__device__ __forceinline__ void cp_commit() {
    asm volatile("cp.async.commit_group;\n");
}
__device__ __forceinline__ void cp_wait0() {
    asm volatile("cp.async.wait_group 0;\n");
}
__device__ __forceinline__ void cp_wait3() {
    asm volatile("cp.async.wait_group 3;\n");
}

// ---------------- attention: cp.async ring + fused combine/pack ----------------

__global__ __launch_bounds__(256, 2) void attn_kernel(
    const float* __restrict__ enc,
    const float* __restrict__ hidden1,
    const float* __restrict__ embed,
    const float* __restrict__ hidden2)
{
    extern __shared__ float ring[];   // [NSTAGE][STAGE_FLOATS]

    const int bx   = blockIdx.x;
    const int tid  = threadIdx.x;
    const int w    = tid >> 5;
    const int lane = tid & 31;

    const int b  = bx >> 1;
    const int sp = bx & 1;

    __shared__ float ctx_s[8][H_];
    __shared__ float d_s[8];
    __shared__ unsigned old_s;

    // transposed static packs (tiny; overlapped with streaming)
    if (sp == 1) {
        g_X2T[tid * B_ + b]          = embed[b * H_ + tid];
        g_X2T[(512 + tid) * B_ + b]  = hidden2[b * H_ + tid];
    } else {
        g_X1T[(H_ + tid) * B_ + b]   = hidden1[b * H_ + tid];
    }

    const float4 ha = *reinterpret_cast<const float4*>(&hidden1[b * H_ + lane * 4]);
    const float4 hb = *reinterpret_cast<const float4*>(&hidden1[b * H_ + 128 + lane * 4]);

    const char* encb = reinterpret_cast<const char*>(
        enc + (size_t)b * (L_ * H_) + (size_t)sp * (LSP * H_));

    // prologue: fill 4 stages (one commit group per stage)
#pragma unroll
    for (int s = 0; s < NSTAGE - 1; s++) {
        char* dst = reinterpret_cast<char*>(ring + s * STAGE_FLOATS) + tid * 16;
        const char* src = encb + (size_t)s * 16384 + tid * 16;
#pragma unroll
        for (int it = 0; it < 4; it++)
            cp_async16(dst + it * 4096, src + it * 4096);
        cp_commit();
    }

    float d = 0.f;
    float c[8];
#pragma unroll
    for (int q = 0; q < 8; q++) c[q] = 0.f;

    for (int s = 0; s < NSTAGES_TOTAL; s++) {
        cp_wait3();           // oldest committed group (stage s) complete
        __syncthreads();      // all warps see stage s; all done with s-1 buffer

        // issue stage s+4 into buffer (s+4)%NSTAGE (freed at s-1)
        const int sn = s + NSTAGE - 1;
        if (sn < NSTAGES_TOTAL) {
            char* dst = reinterpret_cast<char*>(
                ring + (sn % NSTAGE) * STAGE_FLOATS) + tid * 16;
            const char* src = encb + (size_t)sn * 16384 + tid * 16;
#pragma unroll
            for (int it = 0; it < 4; it++)
                cp_async16(dst + it * 4096, src + it * 4096);
            cp_commit();
        }

        // compute: warp w handles rows 2w, 2w+1 of this stage
        const float* sb = ring + (s % NSTAGE) * STAGE_FLOATS;
#pragma unroll
        for (int rr = 0; rr < 2; rr++) {
            const float* rb = sb + (2 * w + rr) * H_;
            float4 ea = *reinterpret_cast<const float4*>(rb + lane * 4);
            float4 eb = *reinterpret_cast<const float4*>(rb + 128 + lane * 4);
            float sc = ea.x * ha.x + ea.y * ha.y + ea.z * ha.z + ea.w * ha.w
                     + eb.x * hb.x + eb.y * hb.y + eb.z * hb.z + eb.w * hb.w;
#pragma unroll
            for (int off = 16; off; off >>= 1)
                sc += __shfl_xor_sync(0xffffffffu, sc, off);
            float es = __expf(sc - M0);
            d += es;
            c[0] = fmaf(es, ea.x, c[0]);
            c[1] = fmaf(es, ea.y, c[1]);
            c[2] = fmaf(es, ea.z, c[2]);
            c[3] = fmaf(es, ea.w, c[3]);
            c[4] = fmaf(es, eb.x, c[4]);
            c[5] = fmaf(es, eb.y, c[5]);
            c[6] = fmaf(es, eb.z, c[6]);
            c[7] = fmaf(es, eb.w, c[7]);
        }
    }

    // block reduce via smem
#pragma unroll
    for (int q = 0; q < 4; q++) {
        ctx_s[w][lane * 4 + q]       = c[q];
        ctx_s[w][128 + lane * 4 + q] = c[4 + q];
    }
    if (lane == 0) d_s[w] = d;
    __syncthreads();

    float D = 0.f, C = 0.f;
#pragma unroll
    for (int ww = 0; ww < 8; ww++) {
        D += d_s[ww];
        C += ctx_s[ww][tid];
    }
    g_ctx_part[bx * H_ + tid] = C;
    if (tid == 0) g_d[bx] = D;

    // ---- last-arriver combine (R10 protocol) ----
    __threadfence();
    __syncthreads();
    if (tid == 0) old_s = atomicAdd(&g_cnt[b], 1u);
    __syncthreads();
    if (old_s == NSPLIT - 1) {
        __threadfence();
        float DD = 0.f, CC = 0.f;
#pragma unroll
        for (int s = 0; s < NSPLIT; s++) {
            DD += g_d[b * NSPLIT + s];
            CC += g_ctx_part[(b * NSPLIT + s) * H_ + tid];
        }
        g_X1T[tid * B_ + b] = CC / DD;
        if (tid == 0) g_cnt[b] = 0u;   // reset for next graph replay
    }
}

// ---------------- full-K LSTM cell (R13 verbatim) -------------------------------

// Block = 2 h-indices (8 gate rows: r = g*2+hl) x 128 batches, grid = 128.
// Warps split K 8-ways. Thread = 4 batches x 8 rows (32 acc).
template <int LAYER>
__global__ __launch_bounds__(256, 1) void lstm_full(
    const float* __restrict__ w_ih, const float* __restrict__ w_hh,
    const float* __restrict__ b_ih, const float* __restrict__ b_hh,
    const float* __restrict__ c_prev,
    float* __restrict__ out)
{
    constexpr int K   = (LAYER == 1) ? 512 : 768;
    constexpr int KIH = (LAYER == 1) ? 256 : 512;   // w_ih column count
    constexpr int KW  = K / 8;                      // per-warp k: 64 / 96
    constexpr int NS  = KW / 8;                     // 8-k stages: 8 / 12
    constexpr int SF  = (8 * K > 8192) ? 8 * K : 8192;

    __shared__ float S[SF];          // Ws [8][K] mainloop; Rs [8r][8w][128b] after
    float* Ws = S;
    float* Rs = S;

    const int tid  = threadIdx.x;
    const int warp = tid >> 5;
    const int lane = tid & 31;
    const int b0   = lane * 4;
    const int h0   = blockIdx.x * 2;

    const float* __restrict__ XT = (LAYER == 1) ? g_X1T : g_X2T;

    const int ehl = tid >> 7;
    const int eb_ = tid & 127;
    float bias[4];
#pragma unroll
    for (int g = 0; g < 4; g++)
        bias[g] = b_ih[g * H_ + h0 + ehl] + b_hh[g * H_ + h0 + ehl];
    const float cpv = c_prev[eb_ * H_ + h0 + ehl];

    const int kbase = warp * KW;

    float4 xv[8], xn[8];
#pragma unroll
    for (int i = 0; i < 8; i++)
        xv[i] = *reinterpret_cast<const float4*>(
            &XT[(size_t)(kbase + i) * 128 + b0]);

    // W prologue: 8 rows x K/4 float4 via cp.async. row r -> gate r>>1, hl r&1
    for (int t = tid; t < 2 * K; t += 256) {
        int r = t / (K / 4);
        int k = (t % (K / 4)) * 4;
        int grow = (r >> 1) * H_ + h0 + (r & 1);
        const float* src = (k < KIH)
            ? &w_ih[(size_t)grow * KIH + k]
            : &w_hh[(size_t)grow * 256 + (k - KIH)];
        cp_async16(&Ws[r * K + k], src);
    }
    cp_commit();
    cp_wait0();
    __syncthreads();

    float acc[4][8];
#pragma unroll
    for (int j = 0; j < 4; j++)
#pragma unroll
        for (int r = 0; r < 8; r++) acc[j][r] = 0.f;

#pragma unroll
    for (int s = 0; s < NS; s++) {
        if (s + 1 < NS) {
#pragma unroll
            for (int i = 0; i < 8; i++)
                xn[i] = *reinterpret_cast<const float4*>(
                    &XT[(size_t)(kbase + (s + 1) * 8 + i) * 128 + b0]);
        }
#pragma unroll
        for (int i = 0; i < 8; i += 4) {
            float wr[8][4];
#pragma unroll
            for (int r = 0; r < 8; r++)
                *reinterpret_cast<float4*>(wr[r]) =
                    *reinterpret_cast<const float4*>(&Ws[r * K + kbase + s * 8 + i]);
#pragma unroll
            for (int kk = 0; kk < 4; kk++) {
                float4 x = xv[i + kk];
#pragma unroll
                for (int r = 0; r < 8; r++) {
                    acc[0][r] = fmaf(x.x, wr[r][kk], acc[0][r]);
                    acc[1][r] = fmaf(x.y, wr[r][kk], acc[1][r]);
                    acc[2][r] = fmaf(x.z, wr[r][kk], acc[2][r]);
                    acc[3][r] = fmaf(x.w, wr[r][kk], acc[3][r]);
                }
            }
        }
        if (s + 1 < NS) {
#pragma unroll
            for (int i = 0; i < 8; i++) xv[i] = xn[i];
        }
    }

    __syncthreads();
#pragma unroll
    for (int r = 0; r < 8; r++)
#pragma unroll
        for (int j = 0; j < 4; j++)
            Rs[(r * 8 + warp) * 128 + b0 + j] = acc[j][r];
    __syncthreads();

    {
        const int h = h0 + ehl;
        float gate[4];
#pragma unroll
        for (int g = 0; g < 4; g++) {
            const int r = g * 2 + ehl;
            float s = bias[g];
#pragma unroll
            for (int w = 0; w < 8; w++)
                s += Rs[(r * 8 + w) * 128 + eb_];
            gate[g] = s;
        }
        float gi = sigmoidf_(gate[0]);
        float gf = sigmoidf_(gate[1]);
        float gg = tanhf(gate[2]);
        float go = sigmoidf_(gate[3]);
        float cn = fmaf(gf, cpv, gi * gg);
        float hn = go * tanhf(cn);

        if (LAYER == 1) {
            out[65536 + eb_ * H_ + h] = cn;    // c1
            out[32768 + eb_ * H_ + h] = hn;    // h1
            g_X2T[(H_ + h) * B_ + eb_] = hn;   // h1T for lstm2 (coalesced)
        } else {
            out[131072 + eb_ * H_ + h] = cn;   // c2
            out[98304 + eb_ * H_ + h]  = hn;   // h2
            out[eb_ * H_ + h]          = hn;   // outputs
        }
    }
}

// ---------------- launch ----------------------------------------------------------

extern "C" void kernel_launch(void* const* d_in, const int* in_sizes, int n_in,
                              void* d_out, int out_size)
{
    const float* embed   = (const float*)d_in[0];
    const float* enc     = (const float*)d_in[1];
    const float* hidden1 = (const float*)d_in[2];
    const float* cell1   = (const float*)d_in[3];
    const float* hidden2 = (const float*)d_in[4];
    const float* cell2   = (const float*)d_in[5];
    const float* w_ih1   = (const float*)d_in[6];
    const float* w_hh1   = (const float*)d_in[7];
    const float* b_ih1   = (const float*)d_in[8];
    const float* b_hh1   = (const float*)d_in[9];
    const float* w_ih2   = (const float*)d_in[10];
    const float* w_hh2   = (const float*)d_in[11];
    const float* b_ih2   = (const float*)d_in[12];
    const float* b_hh2   = (const float*)d_in[13];
    float* out = (float*)d_out;

    static bool attr_set = false;
    if (!attr_set) {
        cudaFuncSetAttribute(attn_kernel,
            cudaFuncAttributeMaxDynamicSharedMemorySize, ATTN_SMEM);
        attr_set = true;
    }

    attn_kernel<<<ATTN_BLOCKS, 256, ATTN_SMEM>>>(enc, hidden1, embed, hidden2);
    lstm_full<1><<<128, 256>>>(w_ih1, w_hh1, b_ih1, b_hh1, cell1, out);
    lstm_full<2><<<128, 256>>>(w_ih2, w_hh2, b_ih2, b_hh2, cell2, out);
}

// round 16
// speedup vs baseline: 1.1750x; 1.1750x over previous
#include <cuda_runtime.h>

// ---------------------------------------------------------------------------
// Decoder step: attention (B=128, L=2048, H=256) + 2x LSTM cell.
//
// attn_kernel : R10's proven version, FROZEN (46.3us, DRAM 74%). grid = 128
//               batches x 2 L-splits = 256 blocks (single wave), contiguous
//               1024 rows/block, register-prefetch stream, one reduce at the
//               end, fixed-offset exp, fused last-arriver combine +
//               transposed packing.
// lstm_full<L>: gates GEMM, grid = 256 = 128 h-pairs x 2 batch-halves
//               (2 blocks/SM: halves per-block FMA to 2.3/3.4us and doubles
//               warps/SM for latency hiding; total L2 X-traffic unchanged).
//               Block = 8 gate rows x 64 batches; warps split K 8-ways;
//               thread tile 2b x 8r (float2 X loads, coalesced);
//               X pipelined LDG, W via cp.async, Ws/Rs overlaid.
// ---------------------------------------------------------------------------

#define B_ 128
#define H_ 256
#define L_ 2048
#define NSPLIT 2
#define LSP (L_ / NSPLIT)           // 1024 rows per split
#define ATTN_BLOCKS (B_ * NSPLIT)   // 256 — single wave
#define M0 44.0f

__device__ float g_X1T[512 * 128];   // rows 0-255 ctx, 256-511 hidden1
__device__ float g_X2T[768 * 128];   // rows 0-255 embed, 256-511 h1, 512-767 hidden2
__device__ float g_ctx_part[ATTN_BLOCKS * H_];
__device__ float g_d[ATTN_BLOCKS];
__device__ unsigned g_cnt[B_];       // zero-init; self-resetting

// ---------------- helpers ----------------------------------------------------

__device__ __forceinline__ void online_step(
    const float4& ea, const float4& eb, const float4& ha, const float4& hb,
    float& d, float* c)
{
    float s = ea.x * ha.x + ea.y * ha.y + ea.z * ha.z + ea.w * ha.w
            + eb.x * hb.x + eb.y * hb.y + eb.z * hb.z + eb.w * hb.w;
#pragma unroll
    for (int off = 16; off; off >>= 1)
        s += __shfl_xor_sync(0xffffffffu, s, off);
    float es = __expf(s - M0);
    d += es;
    c[0] = fmaf(es, ea.x, c[0]);
    c[1] = fmaf(es, ea.y, c[1]);
    c[2] = fmaf(es, ea.z, c[2]);
    c[3] = fmaf(es, ea.w, c[3]);
    c[4] = fmaf(es, eb.x, c[4]);
    c[5] = fmaf(es, eb.y, c[5]);
    c[6] = fmaf(es, eb.z, c[6]);
    c[7] = fmaf(es, eb.w, c[7]);
}

__device__ __forceinline__ float sigmoidf_(float x) {
    return 1.f / (1.f + __expf(-x));
}

__device__ __forceinline__ void cp_async16(void* smem_dst, const void* gmem_src) {
    unsigned saddr = (unsigned)__cvta_generic_to_shared(smem_dst);
    asm volatile("cp.async.cg.shared.global [%0], [%1], 16;\n"
                 :: "r"(saddr), "l"(gmem_src));
}
__device__ __forceinline__ void cp_commit() {
    asm volatile("cp.async.commit_group;\n");
}
__device__ __forceinline__ void cp_wait0() {
    asm volatile("cp.async.wait_group 0;\n");
}

// ---------------- attention + fused combine/pack (R10, frozen) -----------------

__global__ __launch_bounds__(256, 2) void attn_kernel(
    const float* __restrict__ enc,
    const float* __restrict__ hidden1,
    const float* __restrict__ embed,
    const float* __restrict__ hidden2)
{
    const int bx   = blockIdx.x;
    const int tid  = threadIdx.x;
    const int w    = tid >> 5;
    const int lane = tid & 31;

    const int b  = bx >> 1;
    const int sp = bx & 1;

    __shared__ float h1s[H_];
    __shared__ float ctx_s[8][H_];
    __shared__ float d_s[8];
    __shared__ unsigned old_s;

    h1s[tid] = hidden1[b * H_ + tid];

    // transposed static packs (tiny; overlapped with streaming)
    if (sp == 1) {
        g_X2T[tid * B_ + b]          = embed[b * H_ + tid];
        g_X2T[(512 + tid) * B_ + b]  = hidden2[b * H_ + tid];
    }
    __syncthreads();
    if (sp == 0) g_X1T[(H_ + tid) * B_ + b] = h1s[tid];

    const float4 ha = *reinterpret_cast<const float4*>(&h1s[lane * 4]);
    const float4 hb = *reinterpret_cast<const float4*>(&h1s[128 + lane * 4]);

    const float* encb = enc + (size_t)b * (L_ * H_) + (size_t)sp * (LSP * H_);

    float d[4], c[4][8];
    float4 ea[4], eb[4];
    const float* p[4];
#pragma unroll
    for (int j = 0; j < 4; j++) {
        d[j] = 0.f;
#pragma unroll
        for (int q = 0; q < 8; q++) c[j][q] = 0.f;
        p[j]  = encb + (size_t)(w + 8 * j) * H_ + lane * 4;
        ea[j] = *reinterpret_cast<const float4*>(p[j]);
        eb[j] = *reinterpret_cast<const float4*>(p[j] + 128);
    }

    const int STRIDE = 32 * H_;
    const int ITERS  = LSP / 32;          // 32
    for (int i = 0; i < ITERS - 1; i++) {
        float4 na[4], nb[4];
#pragma unroll
        for (int j = 0; j < 4; j++) {
            na[j] = *reinterpret_cast<const float4*>(p[j] + STRIDE);
            nb[j] = *reinterpret_cast<const float4*>(p[j] + STRIDE + 128);
        }
#pragma unroll
        for (int j = 0; j < 4; j++)
            online_step(ea[j], eb[j], ha, hb, d[j], c[j]);
#pragma unroll
        for (int j = 0; j < 4; j++) {
            ea[j] = na[j]; eb[j] = nb[j]; p[j] += STRIDE;
        }
    }
#pragma unroll
    for (int j = 0; j < 4; j++)
        online_step(ea[j], eb[j], ha, hb, d[j], c[j]);

    // merge 4 streams (plain sums)
#pragma unroll
    for (int j = 1; j < 4; j++) {
        d[0] += d[j];
#pragma unroll
        for (int q = 0; q < 8; q++) c[0][q] += c[j][q];
    }

    // block reduce via smem
#pragma unroll
    for (int q = 0; q < 4; q++) {
        ctx_s[w][lane * 4 + q]       = c[0][q];
        ctx_s[w][128 + lane * 4 + q] = c[0][4 + q];
    }
    if (lane == 0) d_s[w] = d[0];
    __syncthreads();

    float D = 0.f, C = 0.f;
#pragma unroll
    for (int ww = 0; ww < 8; ww++) {
        D += d_s[ww];
        C += ctx_s[ww][tid];
    }
    g_ctx_part[bx * H_ + tid] = C;
    if (tid == 0) g_d[bx] = D;

    // ---- last-arriver combine ----
    __threadfence();
    __syncthreads();
    if (tid == 0) old_s = atomicAdd(&g_cnt[b], 1u);
    __syncthreads();
    if (old_s == NSPLIT - 1) {
        __threadfence();
        float DD = 0.f, CC = 0.f;
#pragma unroll
        for (int s = 0; s < NSPLIT; s++) {
            DD += g_d[b * NSPLIT + s];
            CC += g_ctx_part[(b * NSPLIT + s) * H_ + tid];
        }
        g_X1T[tid * B_ + b] = CC / DD;
        if (tid == 0) g_cnt[b] = 0u;   // reset for next graph replay
    }
}

// ---------------- full-K LSTM cell: 2 blocks/SM ---------------------------------

// grid = 256: bid = hp*2 + bh. Block = 8 gate rows (h-pair hp) x 64 batches
// (half bh). Warps split K 8-ways; thread tile 2 batches x 8 rows.
template <int LAYER>
__global__ __launch_bounds__(256, 2) void lstm_full(
    const float* __restrict__ w_ih, const float* __restrict__ w_hh,
    const float* __restrict__ b_ih, const float* __restrict__ b_hh,
    const float* __restrict__ c_prev,
    float* __restrict__ out)
{
    constexpr int K   = (LAYER == 1) ? 512 : 768;
    constexpr int KIH = (LAYER == 1) ? 256 : 512;   // w_ih column count
    constexpr int KW  = K / 8;                      // per-warp k: 64 / 96
    constexpr int NS  = KW / 8;                     // 8-k stages: 8 / 12

    __shared__ float Ws[8 * K];          // 8 gate rows x K
    __shared__ float Rs[8 * 8 * 64];     // [row r][warp][64 batches]

    const int tid  = threadIdx.x;
    const int warp = tid >> 5;
    const int lane = tid & 31;
    const int hp   = blockIdx.x >> 1;
    const int bh   = blockIdx.x & 1;
    const int h0   = hp * 2;
    const int bofs = bh * 64;            // batch base of this block
    const int b0   = bofs + lane * 2;    // this thread's 2 batches

    const float* __restrict__ XT = (LAYER == 1) ? g_X1T : g_X2T;

    // epilogue operand prefetch: threads 0-127 -> (hl = tid>>6, bl = tid&63)
    const int ehl = (tid >> 6) & 1;
    const int ebl = tid & 63;
    const int eb_ = bofs + ebl;
    float bias[4];
    float cpv = 0.f;
    if (tid < 128) {
#pragma unroll
        for (int g = 0; g < 4; g++)
            bias[g] = b_ih[g * H_ + h0 + ehl] + b_hh[g * H_ + h0 + ehl];
        cpv = c_prev[eb_ * H_ + h0 + ehl];
    }

    const int kbase = warp * KW;

    // issue first X batch before W prologue (float2: 2 batches per lane)
    float2 xv[8], xn[8];
#pragma unroll
    for (int i = 0; i < 8; i++)
        xv[i] = *reinterpret_cast<const float2*>(
            &XT[(size_t)(kbase + i) * 128 + b0]);

    // W prologue: 8 rows x K/4 float4 via cp.async. row r -> gate r>>1, hl r&1
    for (int t = tid; t < 2 * K; t += 256) {
        int r = t / (K / 4);
        int k = (t % (K / 4)) * 4;
        int grow = (r >> 1) * H_ + h0 + (r & 1);
        const float* src = (k < KIH)
            ? &w_ih[(size_t)grow * KIH + k]
            : &w_hh[(size_t)grow * 256 + (k - KIH)];
        cp_async16(&Ws[r * K + k], src);
    }
    cp_commit();
    cp_wait0();
    __syncthreads();

    float acc[2][8];   // [batch j][row r]
#pragma unroll
    for (int j = 0; j < 2; j++)
#pragma unroll
        for (int r = 0; r < 8; r++) acc[j][r] = 0.f;

#pragma unroll
    for (int s = 0; s < NS; s++) {
        if (s + 1 < NS) {
#pragma unroll
            for (int i = 0; i < 8; i++)
                xn[i] = *reinterpret_cast<const float2*>(
                    &XT[(size_t)(kbase + (s + 1) * 8 + i) * 128 + b0]);
        }
#pragma unroll
        for (int i = 0; i < 8; i += 4) {
            float wr[8][4];
#pragma unroll
            for (int r = 0; r < 8; r++)
                *reinterpret_cast<float4*>(wr[r]) =
                    *reinterpret_cast<const float4*>(&Ws[r * K + kbase + s * 8 + i]);
#pragma unroll
            for (int kk = 0; kk < 4; kk++) {
                float2 x = xv[i + kk];
#pragma unroll
                for (int r = 0; r < 8; r++) {
                    acc[0][r] = fmaf(x.x, wr[r][kk], acc[0][r]);
                    acc[1][r] = fmaf(x.y, wr[r][kk], acc[1][r]);
                }
            }
        }
        if (s + 1 < NS) {
#pragma unroll
            for (int i = 0; i < 8; i++) xv[i] = xn[i];
        }
    }

    // cross-warp reduce via smem
    __syncthreads();
#pragma unroll
    for (int r = 0; r < 8; r++) {
        float2 v = make_float2(acc[0][r], acc[1][r]);
        *reinterpret_cast<float2*>(&Rs[(r * 8 + warp) * 64 + lane * 2]) = v;
    }
    __syncthreads();

    if (tid < 128) {
        const int h = h0 + ehl;
        float gate[4];
#pragma unroll
        for (int g = 0; g < 4; g++) {
            const int r = g * 2 + ehl;
            float s = bias[g];
#pragma unroll
            for (int w = 0; w < 8; w++)
                s += Rs[(r * 8 + w) * 64 + ebl];
            gate[g] = s;
        }
        float gi = sigmoidf_(gate[0]);
        float gf = sigmoidf_(gate[1]);
        float gg = tanhf(gate[2]);
        float go = sigmoidf_(gate[3]);
        float cn = fmaf(gf, cpv, gi * gg);
        float hn = go * tanhf(cn);

        if (LAYER == 1) {
            out[65536 + eb_ * H_ + h] = cn;    // c1
            out[32768 + eb_ * H_ + h] = hn;    // h1
            g_X2T[(H_ + h) * B_ + eb_] = hn;   // h1T for lstm2 (coalesced)
        } else {
            out[131072 + eb_ * H_ + h] = cn;   // c2
            out[98304 + eb_ * H_ + h]  = hn;   // h2
            out[eb_ * H_ + h]          = hn;   // outputs
        }
    }
}

// ---------------- launch ----------------------------------------------------------

extern "C" void kernel_launch(void* const* d_in, const int* in_sizes, int n_in,
                              void* d_out, int out_size)
{
    const float* embed   = (const float*)d_in[0];
    const float* enc     = (const float*)d_in[1];
    const float* hidden1 = (const float*)d_in[2];
    const float* cell1   = (const float*)d_in[3];
    const float* hidden2 = (const float*)d_in[4];
    const float* cell2   = (const float*)d_in[5];
    const float* w_ih1   = (const float*)d_in[6];
    const float* w_hh1   = (const float*)d_in[7];
    const float* b_ih1   = (const float*)d_in[8];
    const float* b_hh1   = (const float*)d_in[9];
    const float* w_ih2   = (const float*)d_in[10];
    const float* w_hh2   = (const float*)d_in[11];
    const float* b_ih2   = (const float*)d_in[12];
    const float* b_hh2   = (const float*)d_in[13];
    float* out = (float*)d_out;

    attn_kernel<<<ATTN_BLOCKS, 256>>>(enc, hidden1, embed, hidden2);
    lstm_full<1><<<256, 256>>>(w_ih1, w_hh1, b_ih1, b_hh1, cell1, out);
    lstm_full<2><<<256, 256>>>(w_ih2, w_hh2, b_ih2, b_hh2, cell2, out);
}

// round 17
// speedup vs baseline: 1.2187x; 1.0372x over previous
#include <cuda_runtime.h>

// ---------------------------------------------------------------------------
// Decoder step: attention (B=128, L=2048, H=256) + 2x LSTM cell.
//
// attn_kernel : R10's proven version, FROZEN (46us, DRAM 74%). grid = 256
//               (single wave). Adds cudaTriggerProgrammaticLaunchCompletion
//               after each block's partial writes (PDL trigger).
// lstm_full<L>: R16 body (grid=256, 8 gate rows x 64 batches, warps split K
//               8-ways, thread tile 2b x 8r). NEW: launched with PDL
//               (programmatic stream serialization). The attention-
//               independent prologue (W cp.async + bias + c_prev) runs
//               DURING the predecessor's tail; cudaGridDependencySynchronize
//               gates the g_X?T reads. lstm1 -> lstm2 chained the same way.
// ---------------------------------------------------------------------------

#define B_ 128
#define H_ 256
#define L_ 2048
#define NSPLIT 2
#define LSP (L_ / NSPLIT)           // 1024 rows per split
#define ATTN_BLOCKS (B_ * NSPLIT)   // 256 — single wave
#define M0 44.0f

__device__ float g_X1T[512 * 128];   // rows 0-255 ctx, 256-511 hidden1
__device__ float g_X2T[768 * 128];   // rows 0-255 embed, 256-511 h1, 512-767 hidden2
__device__ float g_ctx_part[ATTN_BLOCKS * H_];
__device__ float g_d[ATTN_BLOCKS];
__device__ unsigned g_cnt[B_];       // zero-init; self-resetting

// ---------------- helpers ----------------------------------------------------

__device__ __forceinline__ void online_step(
    const float4& ea, const float4& eb, const float4& ha, const float4& hb,
    float& d, float* c)
{
    float s = ea.x * ha.x + ea.y * ha.y + ea.z * ha.z + ea.w * ha.w
            + eb.x * hb.x + eb.y * hb.y + eb.z * hb.z + eb.w * hb.w;
#pragma unroll
    for (int off = 16; off; off >>= 1)
        s += __shfl_xor_sync(0xffffffffu, s, off);
    float es = __expf(s - M0);
    d += es;
    c[0] = fmaf(es, ea.x, c[0]);
    c[1] = fmaf(es, ea.y, c[1]);
    c[2] = fmaf(es, ea.z, c[2]);
    c[3] = fmaf(es, ea.w, c[3]);
    c[4] = fmaf(es, eb.x, c[4]);
    c[5] = fmaf(es, eb.y, c[5]);
    c[6] = fmaf(es, eb.z, c[6]);
    c[7] = fmaf(es, eb.w, c[7]);
}

__device__ __forceinline__ float sigmoidf_(float x) {
    return 1.f / (1.f + __expf(-x));
}

__device__ __forceinline__ void cp_async16(void* smem_dst, const void* gmem_src) {
    unsigned saddr = (unsigned)__cvta_generic_to_shared(smem_dst);
    asm volatile("cp.async.cg.shared.global [%0], [%1], 16;\n"
                 :: "r"(saddr), "l"(gmem_src));
}
__device__ __forceinline__ void cp_commit() {
    asm volatile("cp.async.commit_group;\n");
}
__device__ __forceinline__ void cp_wait0() {
    asm volatile("cp.async.wait_group 0;\n");
}

// ---------------- attention + fused combine/pack (R10 + PDL trigger) -----------

__global__ __launch_bounds__(256, 2) void attn_kernel(
    const float* __restrict__ enc,
    const float* __restrict__ hidden1,
    const float* __restrict__ embed,
    const float* __restrict__ hidden2)
{
    const int bx   = blockIdx.x;
    const int tid  = threadIdx.x;
    const int w    = tid >> 5;
    const int lane = tid & 31;

    const int b  = bx >> 1;
    const int sp = bx & 1;

    __shared__ float h1s[H_];
    __shared__ float ctx_s[8][H_];
    __shared__ float d_s[8];
    __shared__ unsigned old_s;

    h1s[tid] = hidden1[b * H_ + tid];

    // transposed static packs (tiny; overlapped with streaming)
    if (sp == 1) {
        g_X2T[tid * B_ + b]          = embed[b * H_ + tid];
        g_X2T[(512 + tid) * B_ + b]  = hidden2[b * H_ + tid];
    }
    __syncthreads();
    if (sp == 0) g_X1T[(H_ + tid) * B_ + b] = h1s[tid];

    const float4 ha = *reinterpret_cast<const float4*>(&h1s[lane * 4]);
    const float4 hb = *reinterpret_cast<const float4*>(&h1s[128 + lane * 4]);

    const float* encb = enc + (size_t)b * (L_ * H_) + (size_t)sp * (LSP * H_);

    float d[4], c[4][8];
    float4 ea[4], eb[4];
    const float* p[4];
#pragma unroll
    for (int j = 0; j < 4; j++) {
        d[j] = 0.f;
#pragma unroll
        for (int q = 0; q < 8; q++) c[j][q] = 0.f;
        p[j]  = encb + (size_t)(w + 8 * j) * H_ + lane * 4;
        ea[j] = *reinterpret_cast<const float4*>(p[j]);
        eb[j] = *reinterpret_cast<const float4*>(p[j] + 128);
    }

    const int STRIDE = 32 * H_;
    const int ITERS  = LSP / 32;          // 32
    for (int i = 0; i < ITERS - 1; i++) {
        float4 na[4], nb[4];
#pragma unroll
        for (int j = 0; j < 4; j++) {
            na[j] = *reinterpret_cast<const float4*>(p[j] + STRIDE);
            nb[j] = *reinterpret_cast<const float4*>(p[j] + STRIDE + 128);
        }
#pragma unroll
        for (int j = 0; j < 4; j++)
            online_step(ea[j], eb[j], ha, hb, d[j], c[j]);
#pragma unroll
        for (int j = 0; j < 4; j++) {
            ea[j] = na[j]; eb[j] = nb[j]; p[j] += STRIDE;
        }
    }
#pragma unroll
    for (int j = 0; j < 4; j++)
        online_step(ea[j], eb[j], ha, hb, d[j], c[j]);

    // merge 4 streams (plain sums)
#pragma unroll
    for (int j = 1; j < 4; j++) {
        d[0] += d[j];
#pragma unroll
        for (int q = 0; q < 8; q++) c[0][q] += c[j][q];
    }

    // block reduce via smem
#pragma unroll
    for (int q = 0; q < 4; q++) {
        ctx_s[w][lane * 4 + q]       = c[0][q];
        ctx_s[w][128 + lane * 4 + q] = c[0][4 + q];
    }
    if (lane == 0) d_s[w] = d[0];
    __syncthreads();

    float D = 0.f, C = 0.f;
#pragma unroll
    for (int ww = 0; ww < 8; ww++) {
        D += d_s[ww];
        C += ctx_s[ww][tid];
    }
    g_ctx_part[bx * H_ + tid] = C;
    if (tid == 0) g_d[bx] = D;

#if __CUDA_ARCH__ >= 900
    cudaTriggerProgrammaticLaunchCompletion();   // PDL: let lstm1 pre-launch
#endif

    // ---- last-arriver combine ----
    __threadfence();
    __syncthreads();
    if (tid == 0) old_s = atomicAdd(&g_cnt[b], 1u);
    __syncthreads();
    if (old_s == NSPLIT - 1) {
        __threadfence();
        float DD = 0.f, CC = 0.f;
#pragma unroll
        for (int s = 0; s < NSPLIT; s++) {
            DD += g_d[b * NSPLIT + s];
            CC += g_ctx_part[(b * NSPLIT + s) * H_ + tid];
        }
        g_X1T[tid * B_ + b] = CC / DD;
        if (tid == 0) g_cnt[b] = 0u;   // reset for next graph replay
    }
}

// ---------------- full-K LSTM cell: PDL prologue overlap -------------------------

// grid = 256: bid = hp*2 + bh. Block = 8 gate rows (h-pair hp) x 64 batches
// (half bh). Warps split K 8-ways; thread tile 2 batches x 8 rows.
// Prologue (W cp.async + bias + c_prev) runs BEFORE gridDependencySynchronize.
template <int LAYER>
__global__ __launch_bounds__(256, 2) void lstm_full(
    const float* __restrict__ w_ih, const float* __restrict__ w_hh,
    const float* __restrict__ b_ih, const float* __restrict__ b_hh,
    const float* __restrict__ c_prev,
    float* __restrict__ out)
{
    constexpr int K   = (LAYER == 1) ? 512 : 768;
    constexpr int KIH = (LAYER == 1) ? 256 : 512;   // w_ih column count
    constexpr int KW  = K / 8;                      // per-warp k: 64 / 96
    constexpr int NS  = KW / 8;                     // 8-k stages: 8 / 12

    __shared__ float Ws[8 * K];          // 8 gate rows x K
    __shared__ float Rs[8 * 8 * 64];     // [row r][warp][64 batches]

    const int tid  = threadIdx.x;
    const int warp = tid >> 5;
    const int lane = tid & 31;
    const int hp   = blockIdx.x >> 1;
    const int bh   = blockIdx.x & 1;
    const int h0   = hp * 2;
    const int bofs = bh * 64;
    const int b0   = bofs + lane * 2;

    const float* __restrict__ XT = (LAYER == 1) ? g_X1T : g_X2T;

    // ---------- attention-independent prologue (overlaps predecessor tail) ----
    const int ehl = (tid >> 6) & 1;
    const int ebl = tid & 63;
    const int eb_ = bofs + ebl;
    float bias[4];
    float cpv = 0.f;
    if (tid < 128) {
#pragma unroll
        for (int g = 0; g < 4; g++)
            bias[g] = b_ih[g * H_ + h0 + ehl] + b_hh[g * H_ + h0 + ehl];
        cpv = c_prev[eb_ * H_ + h0 + ehl];
    }

    // W prologue: 8 rows x K/4 float4 via cp.async. row r -> gate r>>1, hl r&1
    for (int t = tid; t < 2 * K; t += 256) {
        int r = t / (K / 4);
        int k = (t % (K / 4)) * 4;
        int grow = (r >> 1) * H_ + h0 + (r & 1);
        const float* src = (k < KIH)
            ? &w_ih[(size_t)grow * KIH + k]
            : &w_hh[(size_t)grow * 256 + (k - KIH)];
        cp_async16(&Ws[r * K + k], src);
    }
    cp_commit();

#if __CUDA_ARCH__ >= 900
    cudaGridDependencySynchronize();     // wait for predecessor's g_X?T writes
#endif
#if __CUDA_ARCH__ >= 900
    if (LAYER == 1) cudaTriggerProgrammaticLaunchCompletion();  // chain lstm2
#endif

    cp_wait0();
    __syncthreads();

    const int kbase = warp * KW;
    float2 xv[8], xn[8];
#pragma unroll
    for (int i = 0; i < 8; i++)
        xv[i] = *reinterpret_cast<const float2*>(
            &XT[(size_t)(kbase + i) * 128 + b0]);

    float acc[2][8];
#pragma unroll
    for (int j = 0; j < 2; j++)
#pragma unroll
        for (int r = 0; r < 8; r++) acc[j][r] = 0.f;

#pragma unroll
    for (int s = 0; s < NS; s++) {
        if (s + 1 < NS) {
#pragma unroll
            for (int i = 0; i < 8; i++)
                xn[i] = *reinterpret_cast<const float2*>(
                    &XT[(size_t)(kbase + (s + 1) * 8 + i) * 128 + b0]);
        }
#pragma unroll
        for (int i = 0; i < 8; i += 4) {
            float wr[8][4];
#pragma unroll
            for (int r = 0; r < 8; r++)
                *reinterpret_cast<float4*>(wr[r]) =
                    *reinterpret_cast<const float4*>(&Ws[r * K + kbase + s * 8 + i]);
#pragma unroll
            for (int kk = 0; kk < 4; kk++) {
                float2 x = xv[i + kk];
#pragma unroll
                for (int r = 0; r < 8; r++) {
                    acc[0][r] = fmaf(x.x, wr[r][kk], acc[0][r]);
                    acc[1][r] = fmaf(x.y, wr[r][kk], acc[1][r]);
                }
            }
        }
        if (s + 1 < NS) {
#pragma unroll
            for (int i = 0; i < 8; i++) xv[i] = xn[i];
        }
    }

    // cross-warp reduce via smem
    __syncthreads();
#pragma unroll
    for (int r = 0; r < 8; r++) {
        float2 v = make_float2(acc[0][r], acc[1][r]);
        *reinterpret_cast<float2*>(&Rs[(r * 8 + warp) * 64 + lane * 2]) = v;
    }
    __syncthreads();

    if (tid < 128) {
        const int h = h0 + ehl;
        float gate[4];
#pragma unroll
        for (int g = 0; g < 4; g++) {
            const int r = g * 2 + ehl;
            float s = bias[g];
#pragma unroll
            for (int w = 0; w < 8; w++)
                s += Rs[(r * 8 + w) * 64 + ebl];
            gate[g] = s;
        }
        float gi = sigmoidf_(gate[0]);
        float gf = sigmoidf_(gate[1]);
        float gg = tanhf(gate[2]);
        float go = sigmoidf_(gate[3]);
        float cn = fmaf(gf, cpv, gi * gg);
        float hn = go * tanhf(cn);

        if (LAYER == 1) {
            out[65536 + eb_ * H_ + h] = cn;    // c1
            out[32768 + eb_ * H_ + h] = hn;    // h1
            g_X2T[(H_ + h) * B_ + eb_] = hn;   // h1T for lstm2 (coalesced)
        } else {
            out[131072 + eb_ * H_ + h] = cn;   // c2
            out[98304 + eb_ * H_ + h]  = hn;   // h2
            out[eb_ * H_ + h]          = hn;   // outputs
        }
    }
}

// ---------------- launch ----------------------------------------------------------

extern "C" void kernel_launch(void* const* d_in, const int* in_sizes, int n_in,
                              void* d_out, int out_size)
{
    const float* embed   = (const float*)d_in[0];
    const float* enc     = (const float*)d_in[1];
    const float* hidden1 = (const float*)d_in[2];
    const float* cell1   = (const float*)d_in[3];
    const float* hidden2 = (const float*)d_in[4];
    const float* cell2   = (const float*)d_in[5];
    const float* w_ih1   = (const float*)d_in[6];
    const float* w_hh1   = (const float*)d_in[7];
    const float* b_ih1   = (const float*)d_in[8];
    const float* b_hh1   = (const float*)d_in[9];
    const float* w_ih2   = (const float*)d_in[10];
    const float* w_hh2   = (const float*)d_in[11];
    const float* b_ih2   = (const float*)d_in[12];
    const float* b_hh2   = (const float*)d_in[13];
    float* out = (float*)d_out;

    attn_kernel<<<ATTN_BLOCKS, 256>>>(enc, hidden1, embed, hidden2);

    // lstm1 / lstm2 with programmatic dependent launch
    cudaLaunchAttribute pdl_attr;
    pdl_attr.id = cudaLaunchAttributeProgrammaticStreamSerialization;
    pdl_attr.val.programmaticStreamSerializationAllowed = 1;

    {
        cudaLaunchConfig_t cfg = {};
        cfg.gridDim  = {256, 1, 1};
        cfg.blockDim = {256, 1, 1};
        cfg.dynamicSmemBytes = 0;
        cfg.stream = 0;
        cfg.attrs = &pdl_attr;
        cfg.numAttrs = 1;
        cudaLaunchKernelEx(&cfg, lstm_full<1>,
                           w_ih1, w_hh1, b_ih1, b_hh1, cell1, out);
    }
    {
        cudaLaunchConfig_t cfg = {};
        cfg.gridDim  = {256, 1, 1};
        cfg.blockDim = {256, 1, 1};
        cfg.dynamicSmemBytes = 0;
        cfg.stream = 0;
        cfg.attrs = &pdl_attr;
        cfg.numAttrs = 1;
        cudaLaunchKernelEx(&cfg, lstm_full<2>,
                           w_ih2, w_hh2, b_ih2, b_hh2, cell2, out);
    }
}